// round 10
// baseline (speedup 1.0000x reference)
#include <cuda_runtime.h>
#include <cuda_bf16.h>
#include <cuda_fp16.h>
#include <cooperative_groups.h>

namespace cg = cooperative_groups;

#define BN_ 32
#define TN_ 1024
#define DN_ 1024
#define ON_ 256
#define CS_ 4
#define SC_ (TN_/CS_)   /* 256 s-rows per CTA */

// ---- device scratch (static: no runtime allocation) ----
__device__ __align__(128) __half         g_UaH[(size_t)BN_*TN_*ON_]; // inputs@Ua + Ba2  (fp16)
__device__ __align__(128) __nv_bfloat16  g_IC [(size_t)BN_*TN_*ON_]; // inputs@Co        (bf16)
__device__ __align__(128) float          g_UoH[(size_t)BN_*TN_*ON_]; // inputs@Uo + Bo2  (fp32)
__device__ float g_w2[ON_];                                           // emb @ Wo

__device__ __forceinline__ float tanh_a(float x){
    float y; asm("tanh.approx.f32 %0, %1;" : "=f"(y) : "f"(x)); return y;
}
__device__ __forceinline__ __half2 tanh2_a(__half2 x){
    unsigned xi = *reinterpret_cast<unsigned*>(&x), r;
    asm("tanh.approx.f16x2 %0, %1;" : "=r"(r) : "r"(xi));
    return *reinterpret_cast<__half2*>(&r);
}
__device__ __forceinline__ void bf8(const uint4 u, float f[8]){
    f[0]=__int_as_float(u.x<<16); f[1]=__int_as_float(u.x&0xffff0000u);
    f[2]=__int_as_float(u.y<<16); f[3]=__int_as_float(u.y&0xffff0000u);
    f[4]=__int_as_float(u.z<<16); f[5]=__int_as_float(u.z&0xffff0000u);
    f[6]=__int_as_float(u.w<<16); f[7]=__int_as_float(u.w&0xffff0000u);
}

// mbarrier cluster barrier (no CCTL.IVALL, unlike cluster.sync)
__device__ __forceinline__ void bar_arrive_rank(unsigned addr, unsigned rank){
    asm volatile("{\n\t.reg .b32 ra;\n\t"
                 "mapa.shared::cluster.u32 ra, %0, %1;\n\t"
                 "mbarrier.arrive.release.cluster.shared::cluster.b64 _, [ra];\n\t}"
                 :: "r"(addr), "r"(rank) : "memory");
}
__device__ __forceinline__ void bar_wait(unsigned addr, unsigned parity){
    unsigned done;
    do {
        asm volatile("{\n\t.reg .pred p;\n\t"
            "mbarrier.try_wait.parity.acquire.cluster.shared::cta.b64 p, [%1], %2, 0x989680;\n\t"
            "selp.b32 %0, 1, 0, p;\n\t}"
            : "=r"(done) : "r"(addr), "r"(parity) : "memory");
    } while (!done);
}

// ================= w2 = emb @ Wo =================
__global__ void __launch_bounds__(256) w2_kernel(const float* __restrict__ emb,
                                                 const float* __restrict__ Wo){
    int w = threadIdx.x >> 5, lane = threadIdx.x & 31;
    int i = blockIdx.x * 8 + w;
    float a = 0.f;
    #pragma unroll
    for (int j = lane; j < ON_; j += 32) a = fmaf(emb[i*ON_+j], Wo[j], a);
    #pragma unroll
    for (int off=16; off; off>>=1) a += __shfl_xor_sync(0xffffffffu, a, off);
    if (lane==0) g_w2[i] = a;
}

// ======= fused precompute: [32768,1024] @ 3x[1024,256] =======
// nt: 0-1 -> Ua (fp16 UaH, +Ba2) | 2-3 -> Co (bf16 IC) | 4-5 -> Uo (f32 UoH, +Bo2)
__global__ void __launch_bounds__(256) gemm_pre(
    const float* __restrict__ A,  const float* __restrict__ Ua,
    const float* __restrict__ Co, const float* __restrict__ Uo,
    const float* __restrict__ Ba2,const float* __restrict__ Bo2)
{
    __shared__ float As[16][128];
    __shared__ float Bs[16][128];
    const int tid = threadIdx.x;
    const int mt = blockIdx.x, nt = blockIdx.y;
    const int which = nt >> 1;
    const int ncol0 = (nt & 1) * 128;
    const float* Bmat = (which==0) ? Ua : ((which==1) ? Co : Uo);
    const int m0 = mt * 128;
    const int tx = tid & 15, ty = tid >> 4;

    float acc[8][8];
    #pragma unroll
    for (int i=0;i<8;i++)
        #pragma unroll
        for (int j=0;j<8;j++) acc[i][j]=0.f;

    for (int k0=0;k0<DN_;k0+=16){
        #pragma unroll
        for (int q=0;q<2;q++){
            int f4 = tid + q*256;
            int row = f4 >> 2, c4 = f4 & 3;
            float4 v = *(const float4*)&A[(size_t)(m0+row)*DN_ + k0 + c4*4];
            As[c4*4+0][row]=v.x; As[c4*4+1][row]=v.y;
            As[c4*4+2][row]=v.z; As[c4*4+3][row]=v.w;
        }
        #pragma unroll
        for (int q=0;q<2;q++){
            int f4 = tid + q*256;
            int kk = f4 >> 5, c4 = f4 & 31;
            *(float4*)&Bs[kk][c4*4] = *(const float4*)&Bmat[(size_t)(k0+kk)*ON_ + ncol0 + c4*4];
        }
        __syncthreads();
        #pragma unroll
        for (int kk=0;kk<16;kk++){
            float a[8], bb[8];
            *(float4*)&a[0]  = *(const float4*)&As[kk][ty*8];
            *(float4*)&a[4]  = *(const float4*)&As[kk][ty*8+4];
            *(float4*)&bb[0] = *(const float4*)&Bs[kk][tx*8];
            *(float4*)&bb[4] = *(const float4*)&Bs[kk][tx*8+4];
            #pragma unroll
            for (int i=0;i<8;i++)
                #pragma unroll
                for (int j=0;j<8;j++) acc[i][j] = fmaf(a[i], bb[j], acc[i][j]);
        }
        __syncthreads();
    }
    #pragma unroll
    for (int i=0;i<8;i++){
        int mrow = m0 + ty*8 + i;
        int trow = mrow & (TN_-1);
        #pragma unroll
        for (int j=0;j<8;j++){
            int c = ncol0 + tx*8 + j;
            float v = acc[i][j];
            size_t oi = (size_t)mrow*ON_ + c;
            if (which==0)      g_UaH[oi] = __float2half(v + Ba2[trow*ON_ + c]);
            else if (which==1) g_IC[oi]  = __float2bfloat16(v);
            else               g_UoH[oi] = v + Bo2[c];
        }
    }
}

// wc swizzle: col j stored at (j/32)*33 + (j%32) -> conflict-free writes AND reads
#define WCI(j) ((((j)>>5)*33) + ((j)&31))

// ============ persistent per-batch cluster recurrence ============
__global__ void __cluster_dims__(CS_,1,1) __launch_bounds__(256,1)
recur_kernel(const float* __restrict__ Wa,  const float* __restrict__ Va,
             const float* __restrict__ Ba1, const float* __restrict__ Ba3,
             const float* __restrict__ Bo3, const float* __restrict__ Bo4,
             float* __restrict__ out)
{
    __shared__ float s_pred[ON_];
    __shared__ float s_q[ON_];
    __shared__ float s_was[ON_];
    __shared__ float s_wasq[64];            // exported WaS quarter
    __shared__ float s_ba3[SC_];
    __shared__ float s_b34[ON_];
    __shared__ float s_w2[ON_];
    __shared__ float s_wc[8][8*33];         // per-warp coc partials (swizzled)
    __shared__ float s_wl[8];
    __shared__ float s_cexp[ON_+1];         // exported: c[256], l
    __shared__ float s_redA[8], s_redB[8];
    __shared__ __align__(16) unsigned long long s_bars[2];

    cg::cluster_group cluster = cg::this_cluster();
    const int rank = blockIdx.x;
    const int b    = blockIdx.y;
    const int tid  = threadIdx.x;
    const int w = tid >> 5, lane = tid & 31;
    const unsigned FULL = 0xffffffffu;

    // ---- one-time init ----
    s_pred[tid] = 0.f;
    s_ba3[tid]  = Ba3[rank*SC_ + tid];
    s_b34[tid]  = Bo3[tid] + Bo4[tid];
    s_w2[tid]   = g_w2[tid];

    // Wa quarter in registers: Wr[jj][k] = Wa[(lane+32k)][rank*64 + w*8 + jj]
    float Wr[8][8];
    #pragma unroll
    for (int jj=0;jj<8;jj++)
        #pragma unroll
        for (int k=0;k<8;k++)
            Wr[jj][k] = Wa[(size_t)(lane + 32*k)*ON_ + rank*64 + w*8 + jj];
    float ba1r[8];
    #pragma unroll
    for (int jj=0;jj<8;jj++) ba1r[jj] = Ba1[rank*64 + w*8 + jj];

    __half2 va_h2[4];
    #pragma unroll
    for (int j=0;j<4;j++)
        va_h2[j] = __floats2half2_rn(Va[lane*8+2*j], Va[lane*8+2*j+1]);

    unsigned barA = (unsigned)__cvta_generic_to_shared(&s_bars[0]);
    unsigned barB = (unsigned)__cvta_generic_to_shared(&s_bars[1]);
    if (tid == 0){
        asm volatile("mbarrier.init.shared.b64 [%0], %1;" :: "r"(barA), "r"(CS_) : "memory");
        asm volatile("mbarrier.init.shared.b64 [%0], %1;" :: "r"(barB), "r"(CS_) : "memory");
    }

    const __half*        uahB = g_UaH + (size_t)b*TN_*ON_ + (size_t)rank*SC_*ON_;
    const __nv_bfloat16* icB  = g_IC  + (size_t)b*TN_*ON_ + (size_t)rank*SC_*ON_;
    const float* uohB = g_UoH + (size_t)b*TN_*ON_;
    float* outB = out + (size_t)b*TN_*ON_;

    const uint4* u4 = (const uint4*)uahB + (size_t)(w*32)*32 + lane;  // row stride = 32 uint4
    const uint4* i4 = (const uint4*)icB  + (size_t)(w*32)*32 + lane;

    const float* peer_wasq[CS_];
    const float* peer_cexp[CS_];
    #pragma unroll
    for (int r=0;r<CS_;r++){
        peer_wasq[r] = (const float*)cluster.map_shared_rank((void*)s_wasq, r);
        peer_cexp[r] = (const float*)cluster.map_shared_rank((void*)s_cexp, r);
    }
    cluster.sync();   // once: mbarrier init + smem init visible cluster-wide

    for (int t=0; t<TN_; t++){
        const unsigned ph = (unsigned)(t & 1);

        // ---- phase 1: q = tanh(pred); woy = softmax(pred)·w2 (no max: pred bounded) ----
        float pv = s_pred[tid];
        s_q[tid] = tanh_a(pv);
        float e  = __expf(pv);
        float en = e, ew = e * s_w2[tid];
        #pragma unroll
        for (int off=16; off; off>>=1){
            en += __shfl_xor_sync(FULL, en, off);
            ew += __shfl_xor_sync(FULL, ew, off);
        }
        if (lane==0){ s_redA[w]=en; s_redB[w]=ew; }
        __syncthreads();
        float sn=0.f, sw=0.f;
        #pragma unroll
        for (int r=0;r<8;r++){ sn+=s_redA[r]; sw+=s_redB[r]; }
        float woy = sw / sn;

        // ---- phase 2: this rank's WaS quarter from registers ----
        float qr[8];
        #pragma unroll
        for (int k=0;k<8;k++) qr[k] = s_q[lane + 32*k];
        #pragma unroll
        for (int jj=0;jj<8;jj++){
            float p = 0.f;
            #pragma unroll
            for (int k=0;k<8;k++) p = fmaf(qr[k], Wr[jj][k], p);
            #pragma unroll
            for (int off=16; off; off>>=1) p += __shfl_xor_sync(FULL, p, off);
            if (lane==0) s_wasq[w*8+jj] = p + ba1r[jj];
        }
        __syncthreads();                       // s_wasq complete CTA-wide
        if (tid < CS_) bar_arrive_rank(barA - 0, (unsigned)tid); // arrive peers' barA
        bar_wait(barA, ph);

        // ---- gather full WaS via DSMEM ----
        s_was[tid] = peer_wasq[tid>>6][tid & 63];
        __syncthreads();
        __half2 was_h2[4];
        #pragma unroll
        for (int j=0;j<4;j++)
            was_h2[j] = __floats2half2_rn(s_was[lane*8+2*j], s_was[lane*8+2*j+1]);

        // ---- phase 5: score + weighted-IC accumulate (no max; 2-deep pipeline) ----
        float l = 0.f, c[8];
        #pragma unroll
        for (int k=0;k<8;k++) c[k]=0.f;

        uint4 uu[2][4], vv[2][4];
        #pragma unroll
        for (int j=0;j<4;j++){ uu[0][j]=u4[(size_t)j*32]; vv[0][j]=__ldcg(&i4[(size_t)j*32]); }
        #pragma unroll 1
        for (int ib=0; ib<8; ib++){
            const int cur = ib & 1, nxt = cur ^ 1;
            if (ib < 7){
                #pragma unroll
                for (int j=0;j<4;j++){
                    uu[nxt][j]=u4[(size_t)((ib+1)*4+j)*32];
                    vv[nxt][j]=__ldcg(&i4[(size_t)((ib+1)*4+j)*32]);
                }
            }
            #pragma unroll
            for (int j=0;j<4;j++){
                const uint4 u = uu[cur][j];
                const __half2* h = reinterpret_cast<const __half2*>(&u);
                __half2 acc = __floats2half2_rn(0.f, 0.f);
                #pragma unroll
                for (int q=0;q<4;q++)
                    acc = __hfma2(tanh2_a(__hadd2(h[q], was_h2[q])), va_h2[q], acc);
                float2 af = __half22float2(acc);
                float p = af.x + af.y;
                #pragma unroll
                for (int off=16; off; off>>=1) p += __shfl_xor_sync(FULL, p, off);
                const int s = w*32 + ib*4 + j;
                float pe = __expf(p + s_ba3[s]);
                l += pe;
                float g[8]; bf8(vv[cur][j], g);
                #pragma unroll
                for (int k=0;k<8;k++) c[k] = fmaf(pe, g[k], c[k]);
            }
        }

        // ---- phase 6: combine 8 warps, export CTA partial ----
        if (lane==0) s_wl[w]=l;
        #pragma unroll
        for (int k=0;k<8;k++) s_wc[w][WCI(lane*8+k)] = c[k];
        __syncthreads();
        {
            float sc=0.f;
            #pragma unroll
            for (int r=0;r<8;r++) sc += s_wc[r][WCI(tid)];
            s_cexp[tid] = sc;
            if (tid==0){
                float sl=0.f;
                #pragma unroll
                for (int r=0;r<8;r++) sl += s_wl[r];
                s_cexp[ON_] = sl;
            }
        }
        __syncthreads();                       // s_cexp complete CTA-wide
        if (tid < CS_) bar_arrive_rank(barB, (unsigned)tid);
        bar_wait(barB, ph);

        // ---- phase 8: cross-CTA combine + pred update (identical all ranks) ----
        float csum=0.f, L=0.f;
        #pragma unroll
        for (int r=0;r<CS_;r++){
            csum += peer_cexp[r][tid];
            L    += peer_cexp[r][ON_];
        }
        float coc = csum / L;
        float uoh = __ldcg(&uohB[(size_t)((t + TN_ - 1) & (TN_-1))*ON_ + tid]);
        float pred = woy + uoh + coc + s_b34[tid];
        if (rank==0) outB[(size_t)t*ON_ + tid] = pred;
        s_pred[tid] = pred;
        // no extra sync needed: phase-1's __syncthreads orders s_pred/s_q reuse
    }
}

extern "C" void kernel_launch(void* const* d_in, const int* in_sizes, int n_in,
                              void* d_out, int out_size) {
    const float* inputs = (const float*)d_in[0];
    const float* Wa  = (const float*)d_in[1];
    const float* Ua  = (const float*)d_in[2];
    const float* Va  = (const float*)d_in[3];
    const float* Ba1 = (const float*)d_in[4];
    const float* Ba2 = (const float*)d_in[5];
    const float* Ba3 = (const float*)d_in[6];
    const float* Wo  = (const float*)d_in[7];
    const float* Uo  = (const float*)d_in[8];
    const float* Co  = (const float*)d_in[9];
    const float* Bo2 = (const float*)d_in[10];
    const float* Bo3 = (const float*)d_in[11];
    const float* Bo4 = (const float*)d_in[12];
    const float* emb = (const float*)d_in[13];
    float* out = (float*)d_out;

    w2_kernel<<<32, 256>>>(emb, Wo);
    gemm_pre<<<dim3((BN_*TN_)/128, 6), 256>>>(inputs, Ua, Co, Uo, Ba2, Bo2);
    recur_kernel<<<dim3(CS_, BN_, 1), 256>>>(Wa, Va, Ba1, Ba3, Bo3, Bo4, out);
}

// round 11
// speedup vs baseline: 1.7437x; 1.7437x over previous
#include <cuda_runtime.h>
#include <cuda_bf16.h>
#include <cuda_fp16.h>
#include <cooperative_groups.h>

namespace cg = cooperative_groups;

#define BN_ 32
#define TN_ 1024
#define DN_ 1024
#define ON_ 256
#define CS_ 4
#define SC_ (TN_/CS_)   /* 256 s-rows per CTA */

// ---- device scratch (static: no runtime allocation) ----
__device__ __align__(128) __half         g_UaH[(size_t)BN_*TN_*ON_]; // inputs@Ua + Ba2  (fp16)
__device__ __align__(128) __nv_bfloat16  g_IC [(size_t)BN_*TN_*ON_]; // inputs@Co        (bf16)
__device__ __align__(128) float          g_UoH[(size_t)BN_*TN_*ON_]; // inputs@Uo + Bo2  (fp32)
__device__ float g_w2[ON_];                                           // emb @ Wo

__device__ __forceinline__ float tanh_a(float x){
    float y; asm("tanh.approx.f32 %0, %1;" : "=f"(y) : "f"(x)); return y;
}
__device__ __forceinline__ __half2 tanh2_a(__half2 x){
    unsigned xi = *reinterpret_cast<unsigned*>(&x), r;
    asm("tanh.approx.f16x2 %0, %1;" : "=r"(r) : "r"(xi));
    return *reinterpret_cast<__half2*>(&r);
}
__device__ __forceinline__ void bf8(const uint4 u, float f[8]){
    f[0]=__int_as_float(u.x<<16); f[1]=__int_as_float(u.x&0xffff0000u);
    f[2]=__int_as_float(u.y<<16); f[3]=__int_as_float(u.y&0xffff0000u);
    f[4]=__int_as_float(u.z<<16); f[5]=__int_as_float(u.z&0xffff0000u);
    f[6]=__int_as_float(u.w<<16); f[7]=__int_as_float(u.w&0xffff0000u);
}

// ---- cluster mbarrier barrier ----
__device__ __forceinline__ void bar_arrive_rank(unsigned addr, unsigned rank){
    asm volatile("{\n\t.reg .b32 ra;\n\t"
                 "mapa.shared::cluster.u32 ra, %0, %1;\n\t"
                 "mbarrier.arrive.release.cluster.shared::cluster.b64 _, [ra];\n\t}"
                 :: "r"(addr), "r"(rank) : "memory");
}
__device__ __forceinline__ void bar_wait(unsigned addr, unsigned parity){
    unsigned done;
    do {
        asm volatile("{\n\t.reg .pred p;\n\t"
            "mbarrier.try_wait.parity.acquire.cluster.shared::cta.b64 p, [%1], %2, 0x989680;\n\t"
            "selp.b32 %0, 1, 0, p;\n\t}"
            : "=r"(done) : "r"(addr), "r"(parity) : "memory");
    } while (!done);
}

// ---- cp.async helpers ----
__device__ __forceinline__ void cp16(unsigned dst, const void* src){
    asm volatile("cp.async.cg.shared.global [%0], [%1], 16;" :: "r"(dst), "l"(src));
}
__device__ __forceinline__ void cp_commit(){
    asm volatile("cp.async.commit_group;" ::: "memory");
}
template<int N> __device__ __forceinline__ void cp_wait(){
    asm volatile("cp.async.wait_group %0;" :: "n"(N) : "memory");
}

// ================= w2 = emb @ Wo =================
__global__ void __launch_bounds__(256) w2_kernel(const float* __restrict__ emb,
                                                 const float* __restrict__ Wo){
    int w = threadIdx.x >> 5, lane = threadIdx.x & 31;
    int i = blockIdx.x * 8 + w;
    float a = 0.f;
    #pragma unroll
    for (int j = lane; j < ON_; j += 32) a = fmaf(emb[i*ON_+j], Wo[j], a);
    #pragma unroll
    for (int off=16; off; off>>=1) a += __shfl_xor_sync(0xffffffffu, a, off);
    if (lane==0) g_w2[i] = a;
}

// ======= fused precompute: [32768,1024] @ 3x[1024,256] =======
__global__ void __launch_bounds__(256,2) gemm_pre(
    const float* __restrict__ A,  const float* __restrict__ Ua,
    const float* __restrict__ Co, const float* __restrict__ Uo,
    const float* __restrict__ Ba2,const float* __restrict__ Bo2)
{
    __shared__ float As[16][128];
    __shared__ float Bs[16][128];
    const int tid = threadIdx.x;
    const int mt = blockIdx.x, nt = blockIdx.y;
    const int which = nt >> 1;
    const int ncol0 = (nt & 1) * 128;
    const float* Bmat = (which==0) ? Ua : ((which==1) ? Co : Uo);
    const int m0 = mt * 128;
    const int tx = tid & 15, ty = tid >> 4;

    float acc[8][8];
    #pragma unroll
    for (int i=0;i<8;i++)
        #pragma unroll
        for (int j=0;j<8;j++) acc[i][j]=0.f;

    for (int k0=0;k0<DN_;k0+=16){
        #pragma unroll
        for (int q=0;q<2;q++){
            int f4 = tid + q*256;
            int row = f4 >> 2, c4 = f4 & 3;
            float4 v = *(const float4*)&A[(size_t)(m0+row)*DN_ + k0 + c4*4];
            As[c4*4+0][row]=v.x; As[c4*4+1][row]=v.y;
            As[c4*4+2][row]=v.z; As[c4*4+3][row]=v.w;
        }
        #pragma unroll
        for (int q=0;q<2;q++){
            int f4 = tid + q*256;
            int kk = f4 >> 5, c4 = f4 & 31;
            *(float4*)&Bs[kk][c4*4] = *(const float4*)&Bmat[(size_t)(k0+kk)*ON_ + ncol0 + c4*4];
        }
        __syncthreads();
        #pragma unroll
        for (int kk=0;kk<16;kk++){
            float a[8], bb[8];
            *(float4*)&a[0]  = *(const float4*)&As[kk][ty*8];
            *(float4*)&a[4]  = *(const float4*)&As[kk][ty*8+4];
            *(float4*)&bb[0] = *(const float4*)&Bs[kk][tx*8];
            *(float4*)&bb[4] = *(const float4*)&Bs[kk][tx*8+4];
            #pragma unroll
            for (int i=0;i<8;i++)
                #pragma unroll
                for (int j=0;j<8;j++) acc[i][j] = fmaf(a[i], bb[j], acc[i][j]);
        }
        __syncthreads();
    }
    #pragma unroll
    for (int i=0;i<8;i++){
        int mrow = m0 + ty*8 + i;
        int trow = mrow & (TN_-1);
        #pragma unroll
        for (int j=0;j<8;j++){
            int c = ncol0 + tx*8 + j;
            float v = acc[i][j];
            size_t oi = (size_t)mrow*ON_ + c;
            if (which==0)      g_UaH[oi] = __float2half(v + Ba2[trow*ON_ + c]);
            else if (which==1) g_IC[oi]  = __float2bfloat16(v);
            else               g_UoH[oi] = v + Bo2[c];
        }
    }
}

#define WCI(j) ((((j)>>5)*33) + ((j)&31))
#define UAH_BYTES (SC_*ON_*2)          /* 131072 */
#define ICR_BYTES (8*2*8*512)          /* 8 warps x 2 stages x 8 rows x 512B = 65536 */
#define DSMEM_BYTES (UAH_BYTES + ICR_BYTES)

// ============ persistent per-batch cluster recurrence ============
__global__ void __cluster_dims__(CS_,1,1) __launch_bounds__(256,1)
recur_kernel(const float* __restrict__ Wa,  const float* __restrict__ Va,
             const float* __restrict__ Ba1, const float* __restrict__ Ba3,
             const float* __restrict__ Bo3, const float* __restrict__ Bo4,
             float* __restrict__ out)
{
    extern __shared__ __align__(128) char dsm[];
    char* s_uahB = dsm;                       // [256][256] fp16, row = 512B
    char* s_icrB = dsm + UAH_BYTES;           // warp w: +w*8192; stage s: +s*4096; row r: +r*512

    __shared__ float s_pred[ON_];
    __shared__ float s_q[ON_];
    __shared__ float s_was[ON_];
    __shared__ float s_wasq[64];
    __shared__ float s_ba3[SC_];
    __shared__ float s_b34[ON_];
    __shared__ float s_w2[ON_];
    __shared__ float s_wc[8][8*33];
    __shared__ float s_wl[8];
    __shared__ float s_cexp[ON_+1];
    __shared__ float s_redA[8], s_redB[8];
    __shared__ __align__(16) unsigned long long s_bars[2];

    cg::cluster_group cluster = cg::this_cluster();
    const int rank = blockIdx.x;
    const int b    = blockIdx.y;
    const int tid  = threadIdx.x;
    const int w = tid >> 5, lane = tid & 31;
    const unsigned FULL = 0xffffffffu;

    // ---- one-time init ----
    s_pred[tid] = 0.f;
    s_ba3[tid]  = Ba3[rank*SC_ + tid];
    s_b34[tid]  = Bo3[tid] + Bo4[tid];
    s_w2[tid]   = g_w2[tid];

    float Wr[8][8];
    #pragma unroll
    for (int jj=0;jj<8;jj++)
        #pragma unroll
        for (int k=0;k<8;k++)
            Wr[jj][k] = Wa[(size_t)(lane + 32*k)*ON_ + rank*64 + w*8 + jj];
    float ba1r[8];
    #pragma unroll
    for (int jj=0;jj<8;jj++) ba1r[jj] = Ba1[rank*64 + w*8 + jj];

    __half2 va_h2[4];
    #pragma unroll
    for (int j=0;j<4;j++)
        va_h2[j] = __floats2half2_rn(Va[lane*8+2*j], Va[lane*8+2*j+1]);

    unsigned barA = (unsigned)__cvta_generic_to_shared(&s_bars[0]);
    unsigned barB = (unsigned)__cvta_generic_to_shared(&s_bars[1]);
    if (tid == 0){
        asm volatile("mbarrier.init.shared.b64 [%0], %1;" :: "r"(barA), "r"(CS_) : "memory");
        asm volatile("mbarrier.init.shared.b64 [%0], %1;" :: "r"(barB), "r"(CS_) : "memory");
    }

    const __half*        uahB = g_UaH + (size_t)b*TN_*ON_ + (size_t)rank*SC_*ON_;
    const __nv_bfloat16* icB  = g_IC  + (size_t)b*TN_*ON_ + (size_t)rank*SC_*ON_;
    const float* uohB = g_UoH + (size_t)b*TN_*ON_;
    float* outB = out + (size_t)b*TN_*ON_;

    // ---- load UaH chunk into smem once ----
    {
        const uint4* src = (const uint4*)uahB;
        uint4* dst = (uint4*)s_uahB;
        #pragma unroll
        for (int i=0;i<32;i++) dst[tid + i*256] = src[tid + i*256];
    }

    // per-warp IC streaming pointers
    unsigned icr = (unsigned)__cvta_generic_to_shared(s_icrB) + w*8192 + lane*16;
    const char* icw = (const char*)icB + (size_t)w*32*512 + lane*16;   // warp's 32 rows
    char* icr_gen = s_icrB + w*8192 + lane*16;                          // generic for reads

    // prefetch chunk0 (stage0) for step 0
    #pragma unroll
    for (int r=0;r<8;r++) cp16(icr + r*512, icw + r*512);
    cp_commit();

    const float* peer_wasq[CS_];
    const float* peer_cexp[CS_];
    #pragma unroll
    for (int r=0;r<CS_;r++){
        peer_wasq[r] = (const float*)cluster.map_shared_rank((void*)s_wasq, r);
        peer_cexp[r] = (const float*)cluster.map_shared_rank((void*)s_cexp, r);
    }
    cluster.sync();   // once: mbarrier init visible cluster-wide

    for (int t=0; t<TN_; t++){
        const unsigned ph = (unsigned)(t & 1);

        // hoist UoH read off the critical path
        float uoh = __ldcg(&uohB[(size_t)((t + TN_ - 1) & (TN_-1))*ON_ + tid]);

        // ---- phase 1: q = tanh(pred); woy = softmax(pred)·w2 ----
        float pv = s_pred[tid];
        s_q[tid] = tanh_a(pv);
        float e  = __expf(pv);
        float en = e, ew = e * s_w2[tid];
        #pragma unroll
        for (int off=16; off; off>>=1){
            en += __shfl_xor_sync(FULL, en, off);
            ew += __shfl_xor_sync(FULL, ew, off);
        }
        if (lane==0){ s_redA[w]=en; s_redB[w]=ew; }
        __syncthreads();
        float sn=0.f, sw=0.f;
        #pragma unroll
        for (int r=0;r<8;r++){ sn+=s_redA[r]; sw+=s_redB[r]; }
        float woy = sw / sn;

        // ---- phase 2: this rank's WaS quarter ----
        float qr[8];
        #pragma unroll
        for (int k=0;k<8;k++) qr[k] = s_q[lane + 32*k];
        #pragma unroll
        for (int jj=0;jj<8;jj++){
            float p = 0.f;
            #pragma unroll
            for (int k=0;k<8;k++) p = fmaf(qr[k], Wr[jj][k], p);
            #pragma unroll
            for (int off=16; off; off>>=1) p += __shfl_xor_sync(FULL, p, off);
            if (lane==0) s_wasq[w*8+jj] = p + ba1r[jj];
        }
        __syncthreads();
        if (tid < CS_) bar_arrive_rank(barA, (unsigned)tid);
        bar_wait(barA, ph);

        // ---- gather full WaS via DSMEM ----
        s_was[tid] = peer_wasq[tid>>6][tid & 63];
        __syncthreads();
        __half2 was_h2[4];
        #pragma unroll
        for (int j=0;j<4;j++)
            was_h2[j] = __floats2half2_rn(s_was[lane*8+2*j], s_was[lane*8+2*j+1]);

        // ---- phase 5: scores from smem UaH + pe·IC from cp.async ring ----
        float l = 0.f, c[8];
        #pragma unroll
        for (int k=0;k<8;k++) c[k]=0.f;

        #pragma unroll
        for (int chunk=0; chunk<4; chunk++){
            // prefetch next chunk (or next step's chunk0)
            if (chunk < 3){
                #pragma unroll
                for (int r=0;r<8;r++)
                    cp16(icr + ((chunk+1)&1)*4096 + r*512, icw + (size_t)((chunk+1)*8+r)*512);
                cp_commit();
                cp_wait<1>();
            } else if (t < TN_-1){
                #pragma unroll
                for (int r=0;r<8;r++)
                    cp16(icr + r*512, icw + r*512);
                cp_commit();
                cp_wait<1>();
            } else {
                cp_wait<0>();
            }
            const char* ring = icr_gen + (chunk&1)*4096;
            #pragma unroll
            for (int r=0;r<8;r++){
                const int row = w*32 + chunk*8 + r;
                uint4 u = *(const uint4*)(s_uahB + (size_t)row*512 + lane*16);
                const __half2* h = reinterpret_cast<const __half2*>(&u);
                __half2 acc = __floats2half2_rn(0.f, 0.f);
                #pragma unroll
                for (int q=0;q<4;q++)
                    acc = __hfma2(tanh2_a(__hadd2(h[q], was_h2[q])), va_h2[q], acc);
                float2 af = __half22float2(acc);
                float p = af.x + af.y;
                #pragma unroll
                for (int off=16; off; off>>=1) p += __shfl_xor_sync(FULL, p, off);
                float pe = __expf(p + s_ba3[row]);
                l += pe;
                uint4 v = *(const uint4*)(ring + r*512);
                float g[8]; bf8(v, g);
                #pragma unroll
                for (int k=0;k<8;k++) c[k] = fmaf(pe, g[k], c[k]);
            }
        }

        // ---- phase 6: combine 8 warps, export CTA partial ----
        if (lane==0) s_wl[w]=l;
        #pragma unroll
        for (int k=0;k<8;k++) s_wc[w][WCI(lane*8+k)] = c[k];
        __syncthreads();
        {
            float sc=0.f;
            #pragma unroll
            for (int r=0;r<8;r++) sc += s_wc[r][WCI(tid)];
            s_cexp[tid] = sc;
            if (tid==0){
                float sl=0.f;
                #pragma unroll
                for (int r=0;r<8;r++) sl += s_wl[r];
                s_cexp[ON_] = sl;
            }
        }
        __syncthreads();
        if (tid < CS_) bar_arrive_rank(barB, (unsigned)tid);
        bar_wait(barB, ph);

        // ---- phase 8: cross-CTA combine + pred update ----
        float csum=0.f, L=0.f;
        #pragma unroll
        for (int r=0;r<CS_;r++){
            csum += peer_cexp[r][tid];
            L    += peer_cexp[r][ON_];
        }
        float coc = csum / L;
        float pred = woy + uoh + coc + s_b34[tid];
        if (rank==0) outB[(size_t)t*ON_ + tid] = pred;
        s_pred[tid] = pred;
    }
}

extern "C" void kernel_launch(void* const* d_in, const int* in_sizes, int n_in,
                              void* d_out, int out_size) {
    const float* inputs = (const float*)d_in[0];
    const float* Wa  = (const float*)d_in[1];
    const float* Ua  = (const float*)d_in[2];
    const float* Va  = (const float*)d_in[3];
    const float* Ba1 = (const float*)d_in[4];
    const float* Ba2 = (const float*)d_in[5];
    const float* Ba3 = (const float*)d_in[6];
    const float* Wo  = (const float*)d_in[7];
    const float* Uo  = (const float*)d_in[8];
    const float* Co  = (const float*)d_in[9];
    const float* Bo2 = (const float*)d_in[10];
    const float* Bo3 = (const float*)d_in[11];
    const float* Bo4 = (const float*)d_in[12];
    const float* emb = (const float*)d_in[13];
    float* out = (float*)d_out;

    static bool attr_done = false;
    if (!attr_done){
        cudaFuncSetAttribute(recur_kernel,
            cudaFuncAttributeMaxDynamicSharedMemorySize, DSMEM_BYTES);
        attr_done = true;
    }

    w2_kernel<<<32, 256>>>(emb, Wo);
    gemm_pre<<<dim3((BN_*TN_)/128, 6), 256>>>(inputs, Ua, Co, Uo, Ba2, Bo2);
    recur_kernel<<<dim3(CS_, BN_, 1), 256, DSMEM_BYTES>>>(Wa, Va, Ba1, Ba3, Bo3, Bo4, out);
}